// round 10
// baseline (speedup 1.0000x reference)
#include <cuda_runtime.h>
#include <cstdint>

typedef unsigned long long ull;

#define BB 32
#define NN 64
#define FF 1280
#define HH 512
#define EE 512
#define VV 10000
#define TT 80
#define G4 2048
#define CHK 32
#define VPAD 10240

#define OFF_H   25600000ll
#define OFF_C   25616384ll
#define OFF_ATT 25632768ll

// ---------------- device state ----------------
__device__ float g_h[2][BB * HH];
__device__ float g_c[2][BB * HH];
__device__ float g_hqp[2][BB * HH];     // hq partials (b1 in ks0)
__device__ float g_gatep[2][BB * FF];   // pre-sigmoid gate partials (bg in ks0)
__device__ float g_ctxg[BB * FF];
__device__ float g_scor[BB * NN];
__device__ float g_mean[BB * FF];
__device__ float g_encproj[BB * NN * HH];
__device__ float g_lgp[2][BB * VPAD];   // logit partials
__device__ float g_gpart[16][BB * G4];  // 0..3 emb, 4..5 Whh, 6..15 Wx-bottom
__device__ float g_hcp[16][BB * HH];    // h0/c0 partials
__device__ ull g_amax[BB];
__device__ unsigned g_cnt, g_epoch;

// ---------------- helpers ----------------
__device__ __forceinline__ ull pk2(float lo, float hi) {
    ull r; asm("mov.b64 %0, {%1,%2};" : "=l"(r) : "f"(lo), "f"(hi)); return r;
}
__device__ __forceinline__ void upk2(ull v, float& lo, float& hi) {
    asm("mov.b64 {%0,%1}, %2;" : "=f"(lo), "=f"(hi) : "l"(v));
}
__device__ __forceinline__ void fma2(ull& d, ull a, ull b) {
    asm("fma.rn.f32x2 %0, %1, %2, %0;" : "+l"(d) : "l"(a), "l"(b));
}
__device__ __forceinline__ float sigf(float x) { return 1.0f / (1.0f + expf(-x)); }
__device__ __forceinline__ unsigned mono32(float f) {
    unsigned u = __float_as_uint(f);
    return (u & 0x80000000u) ? ~u : (u | 0x80000000u);
}
__device__ __forceinline__ uint32_t s2u(const void* p) {
    return (uint32_t)__cvta_generic_to_shared(p);
}
__device__ __forceinline__ void cp16ca(uint32_t dst, const void* src) {
    asm volatile("cp.async.ca.shared.global [%0], [%1], 16;" :: "r"(dst), "l"(src));
}
__device__ __forceinline__ void cp16cg(uint32_t dst, const void* src) {
    asm volatile("cp.async.cg.shared.global [%0], [%1], 16;" :: "r"(dst), "l"(src));
}
__device__ __forceinline__ void cp_commit() { asm volatile("cp.async.commit_group;"); }
template <int n>
__device__ __forceinline__ void cp_wait() {
    asm volatile("cp.async.wait_group %0;" :: "n"(n));
}
__device__ __forceinline__ unsigned ldcgu(const unsigned* p) {
    unsigned v; asm volatile("ld.global.cg.u32 %0, [%1];" : "=r"(v) : "l"(p)); return v;
}

// ---------------- grid barrier (148 co-resident blocks) ----------------
__device__ __forceinline__ void gbar(unsigned target) {
    __threadfence();
    __syncthreads();
    if (threadIdx.x == 0) {
        unsigned old = atomicAdd(&g_cnt, 1u);
        if (old == 147u) {
            g_cnt = 0u;
            __threadfence();
            atomicAdd(&g_epoch, 1u);
        } else {
            while (ldcgu(&g_epoch) < target) __nanosleep(32);
        }
    }
    __syncthreads();
}

// ================= GEMM v10 (persist): no smem, W/A direct-streamed =================
// C[32, 256-col tile] = A[32,K] @ W[K,N].  256 threads (8 warps).
// warp: cg = wid&1 (128 cols), rg = wid>>1 (8 rows); lane: 4 cols (one float4 of W).
// acc[2r+p]: f32x2 over cols (4lane+2p, +1) for row rg*8+r.
// W: direct LDG.128 per k, double-batched (4-k batches).  A: __ldcg float4 row
// batches (4 k per load), one-batch lookahead.  No staging -> no LDGSTS bound.
__device__ __forceinline__ void compute4(ull* acc, const float4* av, const float4* w4) {
#pragma unroll
    for (int u = 0; u < 4; u++) {
        float4 w = w4[u];
        ull w01 = pk2(w.x, w.y);
        ull w23 = pk2(w.z, w.w);
#pragma unroll
        for (int r = 0; r < 8; r++) {
            float a = (u == 0) ? av[r].x : (u == 1) ? av[r].y
                     : (u == 2) ? av[r].z : av[r].w;
            ull ad = pk2(a, a);
            fma2(acc[2 * r], w01, ad);
            fma2(acc[2 * r + 1], w23, ad);
        }
    }
}

template <int K>
__device__ __forceinline__ void gemm10(const float* const* s_rp,
    const float* __restrict__ W, size_t ldw, int N, int bcol, ull* acc)
{
    const int lane = threadIdx.x & 31;
    const int wid = threadIdx.x >> 5;
    const int cg = wid & 1;
    const int rg = wid >> 1;
    __syncthreads();                       // s_rp written by tid<32
    const float* rp[8];
#pragma unroll
    for (int i = 0; i < 8; i++) rp[i] = s_rp[rg * 8 + i];
    const int col = bcol + cg * 128 + lane * 4;
    const bool cok = (col + 3 < N);        // N % 4 == 0 -> all-or-nothing
    const float* Wp = W + col;
    const float4 fz = make_float4(0.f, 0.f, 0.f, 0.f);

    float4 wb0[4], wb1[4], avA[8], avB[8];
#pragma unroll
    for (int u = 0; u < 4; u++)
        wb0[u] = cok ? *(const float4*)(Wp + (size_t)u * ldw) : fz;
#pragma unroll
    for (int u = 0; u < 4; u++)
        wb1[u] = cok ? *(const float4*)(Wp + (size_t)(4 + u) * ldw) : fz;
#pragma unroll
    for (int i = 0; i < 8; i++) avA[i] = __ldcg((const float4*)(rp[i]));

#pragma unroll 1
    for (int k0 = 0; k0 < K; k0 += 8) {
#pragma unroll
        for (int i = 0; i < 8; i++)
            avB[i] = __ldcg((const float4*)(rp[i] + k0 + 4));
        compute4(acc, avA, wb0);
        if (k0 + 8 < K) {
#pragma unroll
            for (int u = 0; u < 4; u++)
                wb0[u] = cok ? *(const float4*)(Wp + (size_t)(k0 + 8 + u) * ldw) : fz;
#pragma unroll
            for (int i = 0; i < 8; i++)
                avA[i] = __ldcg((const float4*)(rp[i] + k0 + 8));
        }
        compute4(acc, avB, wb1);
        if (k0 + 8 < K) {
#pragma unroll
            for (int u = 0; u < 4; u++)
                wb1[u] = cok ? *(const float4*)(Wp + (size_t)(k0 + 12 + u) * ldw) : fz;
        }
    }
}

__device__ __forceinline__ void store10(ull* acc, float* Cp, int ldc, int bcol,
                                        int stN, const float* __restrict__ bias) {
    int lane = threadIdx.x & 31, wid = threadIdx.x >> 5;
    int cg = wid & 1, rg = wid >> 1;
    int col = bcol + cg * 128 + lane * 4;
    if (col + 3 >= stN) return;
    float4 bb = bias ? *(const float4*)(bias + col) : make_float4(0.f, 0.f, 0.f, 0.f);
#pragma unroll
    for (int r = 0; r < 8; r++) {
        float v0, v1, v2, v3;
        upk2(acc[2 * r], v0, v1);
        upk2(acc[2 * r + 1], v2, v3);
        float4 o;
        o.x = v0 + bb.x; o.y = v1 + bb.y; o.z = v2 + bb.z; o.w = v3 + bb.w;
        *(float4*)(Cp + (size_t)(rg * 8 + r) * ldc + col) = o;
    }
}

// ================= GEMM v8 (setup kernels only; one-time cost) =================
#define SWSZ (CHK * 256)
#define SASZ (32 * 40)

__device__ __forceinline__ void fill_w8(const float* Wb, size_t ldw, int ncols,
                                        float* s_wbuf) {
    int tid = threadIdx.x;
#pragma unroll
    for (int p2 = 0; p2 < 8; p2++) {
        int idx = tid + p2 * 256;
        int kk = idx >> 6;
        int c4 = (idx & 63) * 4;
        if (c4 < ncols)
            cp16ca(s2u(s_wbuf + kk * 256 + c4), Wb + (size_t)kk * ldw + c4);
    }
}
__device__ __forceinline__ void fill_a8(const float* const* s_rp, int k0, float* s_abuf) {
    int tid = threadIdx.x;
    int r = tid >> 3, o = (tid & 7) * 4;
    cp16cg(s2u(s_abuf + r * 40 + o), s_rp[r] + k0 + o);
}

template <int K>
__device__ __forceinline__ void gemm8(const float* const* s_rp,
    const float* __restrict__ W, size_t ldw, int N, int bcol,
    ull* acc, float* s_w, float* s_a)
{
    constexpr int C = K / CHK;
    const int tid = threadIdx.x;
    const int lane = tid & 31;
    const int wid = tid >> 5;
    const int ncols = min(256, N - bcol);
    const float* W0 = W + bcol;

    __syncthreads();
    fill_w8(W0, ldw, ncols, s_w);
    fill_a8(s_rp, 0, s_a);
    cp_commit();
    if (C > 1) {
        fill_w8(W0 + (size_t)CHK * ldw, ldw, ncols, s_w + SWSZ);
        fill_a8(s_rp, CHK, s_a + SASZ);
        cp_commit();
    }

    const int chalf = (wid >> 2) * 128;
    const int rg = (wid & 3) * 8;
#pragma unroll 1
    for (int c = 0; c < C; c++) {
        if (c + 1 < C) cp_wait<1>(); else cp_wait<0>();
        __syncthreads();
        const float* sw = s_w + (c & 1) * SWSZ + chalf + lane * 4;
        const float* sa = s_a + (c & 1) * SASZ + rg * 40;
#pragma unroll
        for (int g = 0; g < CHK / 4; g++) {
            float4 w0 = *(const float4*)(sw + (4 * g + 0) * 256);
            float4 w1 = *(const float4*)(sw + (4 * g + 1) * 256);
            float4 w2 = *(const float4*)(sw + (4 * g + 2) * 256);
            float4 w3 = *(const float4*)(sw + (4 * g + 3) * 256);
            float4 av[8];
#pragma unroll
            for (int r = 0; r < 8; r++) av[r] = *(const float4*)(sa + r * 40 + 4 * g);
#pragma unroll
            for (int kk = 0; kk < 4; kk++) {
                float4 wv = (kk == 0) ? w0 : (kk == 1) ? w1 : (kk == 2) ? w2 : w3;
                ull wp0 = pk2(wv.x, wv.y), wp1 = pk2(wv.z, wv.w);
#pragma unroll
                for (int r = 0; r < 8; r++) {
                    float a = (kk == 0) ? av[r].x : (kk == 1) ? av[r].y
                              : (kk == 2) ? av[r].z : av[r].w;
                    ull ad = pk2(a, a);
                    fma2(acc[2 * r], wp0, ad);
                    fma2(acc[2 * r + 1], wp1, ad);
                }
            }
        }
        if (c + 2 < C) {
            __syncthreads();
            fill_w8(W0 + (size_t)(c + 2) * CHK * ldw, ldw, ncols, s_w + (c & 1) * SWSZ);
            fill_a8(s_rp, (c + 2) * CHK, s_a + (c & 1) * SASZ);
            cp_commit();
        }
    }
}

__device__ __forceinline__ void store8(ull* acc, float* Cp, int ldc, int bcol,
                                       int N, const float* __restrict__ bias) {
    int lane = threadIdx.x & 31, wid = threadIdx.x >> 5;
    int col0 = bcol + (wid >> 2) * 128 + lane * 4;
    int row0 = (wid & 3) * 8;
#pragma unroll
    for (int r = 0; r < 8; r++) {
#pragma unroll
        for (int p = 0; p < 2; p++) {
            float x0, x1;
            upk2(acc[2 * r + p], x0, x1);
            int c0 = col0 + 2 * p;
            if (c0 < N)
                Cp[(size_t)(row0 + r) * ldc + c0] = x0 + (bias ? bias[c0] : 0.f);
            if (c0 + 1 < N)
                Cp[(size_t)(row0 + r) * ldc + c0 + 1] = x1 + (bias ? bias[c0 + 1] : 0.f);
        }
    }
}

// ---------------- setup kernels ----------------
__global__ void __launch_bounds__(256) k_mean(const float* __restrict__ feat) {
    int b = blockIdx.x, f = blockIdx.y * 256 + threadIdx.x;
    const float* fb = feat + (size_t)b * NN * FF + f;
    float s = 0.f;
#pragma unroll 16
    for (int n = 0; n < NN; n++) s += fb[(size_t)n * FF];
    g_mean[b * FF + f] = s * (1.0f / NN);
    if (threadIdx.x == 0 && blockIdx.y == 0) g_amax[b] = (ull)(0xFFFFFFFFu - 1u);
    if (b == 0 && blockIdx.y == 0 && threadIdx.x == 0) { g_cnt = 0u; g_epoch = 0u; }
}

__global__ void __launch_bounds__(256) k_hc0(const float* __restrict__ Wh,
                                             const float* __restrict__ Wc) {
    extern __shared__ float sd[];
    __shared__ const float* s_rp[32];
    int m = blockIdx.x >> 4, v = blockIdx.x & 15;
    int ct = v >> 3, ks = v & 7;
    int koff = ks * 160;
    if (threadIdx.x < 32) s_rp[threadIdx.x] = g_mean + threadIdx.x * FF + koff;
    ull acc[16] = {};
    gemm8<160>(s_rp, (m ? Wc : Wh) + (size_t)koff * HH, HH, HH, ct * 256,
               acc, sd, sd + 2 * SWSZ);
    store8(acc, g_hcp[m * 8 + ks], HH, ct * 256, HH, nullptr);
}

__global__ void __launch_bounds__(256) k_hc0r(const float* __restrict__ bh,
                                              const float* __restrict__ bc) {
    int i = blockIdx.x * 256 + threadIdx.x;
    int j = i & 511;
    float sh = bh[j], sc = bc[j];
#pragma unroll
    for (int ks = 0; ks < 8; ks++) { sh += g_hcp[ks][i]; sc += g_hcp[8 + ks][i]; }
    g_h[0][i] = sh;
    g_c[0][i] = sc;
}

__global__ void __launch_bounds__(256) k_encproj(const float* __restrict__ feat,
                                                 const float* __restrict__ W2,
                                                 const float* __restrict__ b2) {
    extern __shared__ float sd[];
    __shared__ const float* s_rp[32];
    int bg = blockIdx.x >> 1, ct = blockIdx.x & 1;
    if (threadIdx.x < 32)
        s_rp[threadIdx.x] = feat + (size_t)(bg * 32 + threadIdx.x) * FF;
    ull acc[16] = {};
    gemm8<FF>(s_rp, W2, HH, HH, ct * 256, acc, sd, sd + 2 * SWSZ);
    store8(acc, g_encproj + (size_t)bg * 32 * HH, HH, ct * 256, HH, b2);
}

// ---------------- THE persistent kernel ----------------
__global__ void __launch_bounds__(256) k_persist(
    const float* __restrict__ feat, const float* __restrict__ emb,
    const float* __restrict__ W1, const float* __restrict__ b1,
    const float* __restrict__ Wg, const float* __restrict__ bg,
    const float* __restrict__ Wx, const float* __restrict__ Whh,
    const float* __restrict__ blstm,
    const float* __restrict__ Wout, const float* __restrict__ bout,
    const float* __restrict__ Va, float* __restrict__ out)
{
    __shared__ const float* s_rp[32];
    __shared__ float s_sm[NN + 8];
    const int bx = blockIdx.x, tid = threadIdx.x;
    const int lane = tid & 31, wid = tid >> 5;
    unsigned ep = 0;

    for (int t = 0;; t++) {
        const int p = t & 1;

        // ---- P1: 110 GEMM units on h(t): hq, gate, Whh, Wout-partials ----
        {
            int id = bx;
            bool run = (id < 110);
            if (t == TT && id < 30) run = false;
            if (t == 0 && id >= 30) run = false;
            if (run) {
                ull acc[16] = {};
                int koff, bcol, N, ldc, stN;
                size_t ldw;
                const float* W;
                const float* bias = nullptr;
                float* dst;
                if (id < 4) {
                    int ct = id >> 1, ks = id & 1;
                    koff = ks * 256; bcol = ct * 256;
                    W = W1 + (size_t)koff * HH; ldw = HH;
                    dst = g_hqp[ks]; ldc = HH; N = HH; stN = HH;
                    if (ks == 0) bias = b1;
                } else if (id < 14) {
                    int v = id - 4, ct = v >> 1, ks = v & 1;
                    koff = ks * 256; bcol = ct * 256;
                    W = Wg + (size_t)koff * FF; ldw = FF;
                    dst = g_gatep[ks]; ldc = FF; N = FF; stN = FF;
                    if (ks == 0) bias = bg;
                } else if (id < 30) {
                    int v = id - 14, ct = v >> 1, ks = v & 1;
                    koff = ks * 256; bcol = ct * 256;
                    W = Whh + (size_t)koff * G4; ldw = G4;
                    dst = g_gpart[4 + ks]; ldc = G4; N = G4; stN = G4;
                } else {
                    int v = id - 30, ct = v >> 1, ks = v & 1;
                    koff = ks * 256; bcol = ct * 256;
                    W = Wout + (size_t)koff * VV; ldw = VV;
                    dst = g_lgp[ks]; ldc = VPAD; N = VV; stN = VPAD;
                }
                if (tid < 32) s_rp[tid] = g_h[p] + tid * HH + koff;
                gemm10<256>(s_rp, W, ldw, N, bcol, acc);
                store10(acc, dst, ldc, bcol, stN, bias);
            }
        }
        gbar(++ep);

        // ---- P2: logits finalize + argmax  ||  Bahdanau scores ----
        if (bx < 79) {
            if (t > 0) {
                const int tt = t - 1;
                int base = bx * 128;
#pragma unroll
                for (int rr = 0; rr < 4; rr++) {
                    int row = wid * 4 + rr;
                    int cc4 = base + lane * 4;
                    ull best = 0ull;
                    if (cc4 + 4 <= VV) {
                        float4 p0 = __ldcg((const float4*)(g_lgp[0] + (size_t)row * VPAD + cc4));
                        float4 p1 = __ldcg((const float4*)(g_lgp[1] + (size_t)row * VPAD + cc4));
                        float4 bo = *(const float4*)(bout + cc4);
                        float4 v;
                        v.x = p0.x + p1.x + bo.x; v.y = p0.y + p1.y + bo.y;
                        v.z = p0.z + p1.z + bo.z; v.w = p0.w + p1.w + bo.w;
                        *(float4*)(out + ((size_t)row * TT + tt) * VV + cc4) = v;
                        float vv[4] = {v.x, v.y, v.z, v.w};
#pragma unroll
                        for (int q = 0; q < 4; q++) {
                            ull key = ((ull)mono32(vv[q]) << 32) |
                                      (0xFFFFFFFFu - (unsigned)(cc4 + q));
                            if (key > best) best = key;
                        }
                    } else {
#pragma unroll
                        for (int q = 0; q < 4; q++) {
                            int cc = cc4 + q;
                            if (cc < VV) {
                                float v = __ldcg(&g_lgp[0][(size_t)row * VPAD + cc]) +
                                          __ldcg(&g_lgp[1][(size_t)row * VPAD + cc]) +
                                          bout[cc];
                                out[((size_t)row * TT + tt) * VV + cc] = v;
                                ull key = ((ull)mono32(v) << 32) |
                                          (0xFFFFFFFFu - (unsigned)cc);
                                if (key > best) best = key;
                            }
                        }
                    }
#pragma unroll
                    for (int m = 16; m; m >>= 1) {
                        ull o = __shfl_xor_sync(0xffffffffu, best, m);
                        if (o > best) best = o;
                    }
                    if (lane == 0) atomicMax(&g_amax[row], best);
                }
            }
        } else if (t < TT) {
            for (int j = (bx - 79) * 8 + wid; j < BB * NN; j += 69 * 8) {
                int b = j >> 6, n = j & 63;
                const float4* ep4 = (const float4*)(g_encproj + ((size_t)b * NN + n) * HH);
                const float4* h0 = (const float4*)(g_hqp[0] + b * HH);
                const float4* h1 = (const float4*)(g_hqp[1] + b * HH);
                const float4* va = (const float4*)Va;
                float s = 0.f;
#pragma unroll
                for (int i = 0; i < 4; i++) {
                    int e4 = lane + 32 * i;
                    float4 v = ep4[e4];
                    float4 q0 = __ldcg(h0 + e4);
                    float4 q1 = __ldcg(h1 + e4);
                    float4 a4 = va[e4];
                    s += fmaxf(v.x + q0.x + q1.x, 0.f) * a4.x;
                    s += fmaxf(v.y + q0.y + q1.y, 0.f) * a4.y;
                    s += fmaxf(v.z + q0.z + q1.z, 0.f) * a4.z;
                    s += fmaxf(v.w + q0.w + q1.w, 0.f) * a4.w;
                }
#pragma unroll
                for (int m = 16; m; m >>= 1) s += __shfl_xor_sync(0xffffffffu, s, m);
                if (lane == 0) g_scor[b * NN + n] = s;
            }
        }
        if (t == TT) return;
        gbar(++ep);

        // ---- P3: emb-GEMM (token) || softmax + gated context ----
        if (bx < 32) {
            if (tid < 32) {
                unsigned tok = 0xFFFFFFFFu -
                               (unsigned)(__ldcg(&g_amax[tid]) & 0xFFFFFFFFull);
                s_rp[tid] = emb + (size_t)tok * EE + (bx & 3) * 128;
            }
            ull acc[16] = {};
            int ct = bx >> 2, ks = bx & 3;
            gemm10<128>(s_rp, Wx + (size_t)(ks * 128) * G4, G4, G4, ct * 256, acc);
            store10(acc, g_gpart[ks], G4, ct * 256, G4, ks == 0 ? blstm : nullptr);
        } else {
            float* s_wv = s_sm;
            float* s_red = s_sm + NN;
            for (int u = bx - 32; u < 160; u += 116) {
                int b = u / 5, fc = u - b * 5;
                __syncthreads();
                float v = 0.f;
                if (tid < 64) v = __ldcg(&g_scor[b * NN + tid]);
                float m = v;
#pragma unroll
                for (int s = 16; s; s >>= 1)
                    m = fmaxf(m, __shfl_xor_sync(0xffffffffu, m, s));
                if (tid < 64 && lane == 0) s_red[tid >> 5] = m;
                __syncthreads();
                if (tid < 64) {
                    float e = __expf(v - fmaxf(s_red[0], s_red[1]));
                    s_wv[tid] = e;
                    float sum = e;
#pragma unroll
                    for (int s = 16; s; s >>= 1)
                        sum += __shfl_xor_sync(0xffffffffu, sum, s);
                    if (lane == 0) s_red[2 + (tid >> 5)] = sum;
                }
                __syncthreads();
                float inv = 1.0f / (s_red[2] + s_red[3]);
                int f = fc * 256 + tid;
                const float* fb = feat + (size_t)b * NN * FF + f;
                float a = 0.f;
#pragma unroll 16
                for (int n = 0; n < NN; n++) a += s_wv[n] * fb[(size_t)n * FF];
                a *= inv;
                float gt = sigf(__ldcg(&g_gatep[0][b * FF + f]) +
                                __ldcg(&g_gatep[1][b * FF + f]));
                g_ctxg[b * FF + f] = a * gt;
                if (fc == 0 && tid < 64)
                    out[OFF_ATT + ((size_t)b * TT + t) * NN + tid] = s_wv[tid] * inv;
            }
        }
        gbar(++ep);

        // ---- P4: Wx-bottom 8 col-tiles x 10 k-slices of 128 ----
        if (bx < 80) {
            int ct = bx / 10, ks = bx - ct * 10;
            if (tid < 32) s_rp[tid] = g_ctxg + tid * FF + ks * 128;
            ull acc[16] = {};
            gemm10<128>(s_rp, Wx + (size_t)(EE + ks * 128) * G4, G4, G4, ct * 256, acc);
            store10(acc, g_gpart[6 + ks], G4, ct * 256, G4, nullptr);
        }
        gbar(++ep);

        // ---- P5: LSTM pointwise (sum 16 partials) + amax reset ----
        if (bx < 64) {
            int b = bx >> 1;
            int j = (bx & 1) * 256 + tid;
            float v[4];
#pragma unroll
            for (int g = 0; g < 4; g++) {
                float s = 0.f;
#pragma unroll
                for (int pt = 0; pt < 16; pt++)
                    s += __ldcg(&g_gpart[pt][b * G4 + g * HH + j]);
                v[g] = s;
            }
            float c_old = __ldcg(&g_c[p][b * HH + j]);
            float c2 = sigf(v[1]) * c_old + sigf(v[0]) * tanhf(v[2]);
            float h2 = sigf(v[3]) * tanhf(c2);
            g_c[p ^ 1][b * HH + j] = c2;
            g_h[p ^ 1][b * HH + j] = h2;
            if (t == TT - 1) {
                out[OFF_H + b * HH + j] = h2;
                out[OFF_C + b * HH + j] = c2;
            }
            if ((bx & 1) == 0 && tid == 0) g_amax[b] = 0ull;
        }
        gbar(++ep);
    }
}

// ---------------- launch ----------------
extern "C" void kernel_launch(void* const* d_in, const int* in_sizes, int n_in,
                              void* d_out, int out_size)
{
    int off = (n_in >= 21) ? 1 : 0;
    const float* feat  = (const float*)d_in[0];
    const float* emb   = (const float*)d_in[2 + off];
    const float* W1    = (const float*)d_in[3 + off];
    const float* b1    = (const float*)d_in[4 + off];
    const float* W2    = (const float*)d_in[5 + off];
    const float* b2    = (const float*)d_in[6 + off];
    const float* Va    = (const float*)d_in[7 + off];
    const float* Wh    = (const float*)d_in[9 + off];
    const float* bh    = (const float*)d_in[10 + off];
    const float* Wc    = (const float*)d_in[11 + off];
    const float* bc    = (const float*)d_in[12 + off];
    const float* Wg    = (const float*)d_in[13 + off];
    const float* bg    = (const float*)d_in[14 + off];
    const float* Wx    = (const float*)d_in[15 + off];
    const float* Whh   = (const float*)d_in[16 + off];
    const float* blstm = (const float*)d_in[17 + off];
    const float* Wout  = (const float*)d_in[18 + off];
    const float* bout  = (const float*)d_in[19 + off];
    float* out = (float*)d_out;

    const int SMEM = (2 * SWSZ + 2 * SASZ) * 4;   // 75,776 B (setup kernels only)
    cudaFuncSetAttribute(k_encproj, cudaFuncAttributeMaxDynamicSharedMemorySize, SMEM);
    cudaFuncSetAttribute(k_hc0, cudaFuncAttributeMaxDynamicSharedMemorySize, SMEM);

    k_mean<<<dim3(BB, 5), 256>>>(feat);
    k_hc0<<<32, 256, SMEM>>>(Wh, Wc);
    k_hc0r<<<64, 256>>>(bh, bc);
    k_encproj<<<128, 256, SMEM>>>(feat, W2, b2);
    k_persist<<<148, 256>>>(feat, emb, W1, b1, Wg, bg, Wx, Whh, blstm,
                            Wout, bout, Va, out);
}

// round 11
// speedup vs baseline: 1.8227x; 1.8227x over previous
#include <cuda_runtime.h>
#include <cstdint>

typedef unsigned long long ull;

#define BB 32
#define NN 64
#define FF 1280
#define HH 512
#define EE 512
#define VV 10000
#define TT 80
#define G4 2048
#define VPAD 10240

// R8-style persist GEMM core
#define KC 64
#define PAD 36
#define WBQ (KC * 256)        // 16384 floats per W buffer

// gemm8 setup core
#define CHK 32
#define SWSZ (CHK * 256)
#define SASZ (32 * 40)

#define OFF_H   25600000ll
#define OFF_C   25616384ll
#define OFF_ATT 25632768ll

// ---------------- device state ----------------
__device__ float g_h[2][BB * HH];
__device__ float g_c[2][BB * HH];
__device__ float g_hqp[2][BB * HH];     // hq partials (b1 in ks0)
__device__ float g_gatep[2][BB * FF];   // pre-sigmoid gate partials (bg in ks0)
__device__ float g_ctxg[BB * FF];
__device__ float g_scor[BB * NN];
__device__ float g_mean[BB * FF];
__device__ float g_encproj[BB * NN * HH];
__device__ float g_lgp[2][BB * VPAD];   // logit partials
__device__ float g_gpart[16][BB * G4];  // 0..3 emb, 4..5 Whh, 6..15 Wx-bottom
__device__ float g_hcp[16][BB * HH];    // h0/c0 partials
__device__ ull g_amax[BB];
__device__ unsigned g_cnt, g_epoch;

// ---------------- helpers ----------------
__device__ __forceinline__ ull pk2(float lo, float hi) {
    ull r; asm("mov.b64 %0, {%1,%2};" : "=l"(r) : "f"(lo), "f"(hi)); return r;
}
__device__ __forceinline__ void upk2(ull v, float& lo, float& hi) {
    asm("mov.b64 {%0,%1}, %2;" : "=f"(lo), "=f"(hi) : "l"(v));
}
__device__ __forceinline__ void fma2(ull& d, ull a, ull b) {
    asm("fma.rn.f32x2 %0, %1, %2, %0;" : "+l"(d) : "l"(a), "l"(b));
}
__device__ __forceinline__ float sigf(float x) { return 1.0f / (1.0f + expf(-x)); }
__device__ __forceinline__ unsigned mono32(float f) {
    unsigned u = __float_as_uint(f);
    return (u & 0x80000000u) ? ~u : (u | 0x80000000u);
}
__device__ __forceinline__ uint32_t s2u(const void* p) {
    return (uint32_t)__cvta_generic_to_shared(p);
}
__device__ __forceinline__ void cp16ca(uint32_t dst, const void* src) {
    asm volatile("cp.async.ca.shared.global [%0], [%1], 16;" :: "r"(dst), "l"(src));
}
__device__ __forceinline__ void cp16cg(uint32_t dst, const void* src) {
    asm volatile("cp.async.cg.shared.global [%0], [%1], 16;" :: "r"(dst), "l"(src));
}
__device__ __forceinline__ void cp_commit() { asm volatile("cp.async.commit_group;"); }
template <int n>
__device__ __forceinline__ void cp_wait() {
    asm volatile("cp.async.wait_group %0;" :: "n"(n));
}
__device__ __forceinline__ unsigned ldcgu(const unsigned* p) {
    unsigned v; asm volatile("ld.global.cg.u32 %0, [%1];" : "=r"(v) : "l"(p)); return v;
}

// ---------------- grid barrier (148 co-resident blocks) ----------------
__device__ __forceinline__ void gbar(unsigned target) {
    __threadfence();
    __syncthreads();
    if (threadIdx.x == 0) {
        unsigned old = atomicAdd(&g_cnt, 1u);
        if (old == 147u) {
            g_cnt = 0u;
            __threadfence();
            atomicAdd(&g_epoch, 1u);
        } else {
            while (ldcgu(&g_epoch) < target) __nanosleep(32);
        }
    }
    __syncthreads();
}

// ================= GEMM vQ (persist): R8 cp.async core, 256-col tiles ==========
// C[32, 256-col tile] = A[32,K] @ W[K,N].  256 threads (8 warps).
// warp: chalf = wid&1 (128 cols), rg = (wid>>1)*8 (8 rows); lane: 4 cols.
// acc[2r(+1)] (r=0..7): f32x2 col pairs for row rg+r.
// W: cp.async.ca double-buffered 64-k chunks.  A: staged ONCE flat (MLP-8),
// s_a[k*PAD + r]; two broadcast LDS.128 per warp-k.
__device__ __forceinline__ void fill_wq(const float* Wb, size_t ldw, int ncols,
                                        float* s_wbuf) {
    int tid = threadIdx.x;
    int kk = tid >> 6;             // 0..3
    int c4 = (tid & 63) * 4;       // 0..252
#pragma unroll
    for (int p = 0; p < 16; p++) {
        int kr = kk + p * 4;
        if (c4 < ncols)
            cp16ca(s2u(s_wbuf + kr * 256 + c4), Wb + (size_t)kr * ldw + c4);
    }
    cp_commit();
}

template <int K, class AElem>
__device__ __forceinline__ void gemmq(AElem aelem, const float* __restrict__ W,
    size_t ldw, int N, int bcol, ull* acc, float* s_dyn)
{
    constexpr int C = K / KC;
    const int tid = threadIdx.x;
    const int lane = tid & 31;
    const int wid = tid >> 5;
    float* s_w = s_dyn;
    float* s_a = s_dyn + 2 * WBQ;
    const int ncols = min(256, N - bcol);
    const float* W0 = W + bcol;

    __syncthreads();               // prior-phase smem reads done; s_tok visible
    fill_wq(W0, ldw, ncols, s_w);
    if (C > 1) fill_wq(W0 + (size_t)KC * ldw, ldw, ncols, s_w + WBQ);

#pragma unroll 8
    for (int idx = tid; idx < 32 * K; idx += 256) {
        int r = idx / K, k = idx - r * K;
        s_a[k * PAD + r] = aelem(r, k);
    }

    const int chalf = (wid & 1) * 128;
    const int rg = (wid >> 1) * 8;
    const float* sa0 = s_a + rg;
#pragma unroll 1
    for (int c = 0; c < C; c++) {
        if (c + 1 < C) cp_wait<1>(); else cp_wait<0>();
        __syncthreads();
        const float* sw = s_w + (c & 1) * WBQ + chalf + lane * 4;
        const float* sac = sa0 + c * KC * PAD;
#pragma unroll 8
        for (int kk = 0; kk < KC; kk++) {
            float4 w4 = *(const float4*)(sw + kk * 256);
            float4 a0 = *(const float4*)(sac + kk * PAD);
            float4 a1 = *(const float4*)(sac + kk * PAD + 4);
            ull w01 = pk2(w4.x, w4.y), w23 = pk2(w4.z, w4.w);
#pragma unroll
            for (int r = 0; r < 4; r++) {
                float a = (r == 0) ? a0.x : (r == 1) ? a0.y : (r == 2) ? a0.z : a0.w;
                ull ad = pk2(a, a);
                fma2(acc[2 * r], w01, ad);
                fma2(acc[2 * r + 1], w23, ad);
            }
#pragma unroll
            for (int r = 0; r < 4; r++) {
                float a = (r == 0) ? a1.x : (r == 1) ? a1.y : (r == 2) ? a1.z : a1.w;
                ull ad = pk2(a, a);
                fma2(acc[8 + 2 * r], w01, ad);
                fma2(acc[8 + 2 * r + 1], w23, ad);
            }
        }
        if (c + 2 < C) {
            __syncthreads();
            fill_wq(W0 + (size_t)(c + 2) * KC * ldw, ldw, ncols, s_w + (c & 1) * WBQ);
        }
    }
}

__device__ __forceinline__ void storeq(ull* acc, float* Cp, int ldc, int bcol,
                                       int stN, const float* __restrict__ bias) {
    int lane = threadIdx.x & 31, wid = threadIdx.x >> 5;
    int col = bcol + (wid & 1) * 128 + lane * 4;
    int rg = (wid >> 1) * 8;
    if (col + 3 >= stN) return;
    float4 bb = bias ? *(const float4*)(bias + col) : make_float4(0.f, 0.f, 0.f, 0.f);
#pragma unroll
    for (int r = 0; r < 8; r++) {
        float v0, v1, v2, v3;
        upk2(acc[2 * r], v0, v1);
        upk2(acc[2 * r + 1], v2, v3);
        float4 o;
        o.x = v0 + bb.x; o.y = v1 + bb.y; o.z = v2 + bb.z; o.w = v3 + bb.w;
        *(float4*)(Cp + (size_t)(rg + r) * ldc + col) = o;
    }
}

// ================= GEMM v8 (setup kernels only) =================
__device__ __forceinline__ void fill_w8(const float* Wb, size_t ldw, int ncols,
                                        float* s_wbuf) {
    int tid = threadIdx.x;
#pragma unroll
    for (int p2 = 0; p2 < 8; p2++) {
        int idx = tid + p2 * 256;
        int kk = idx >> 6;
        int c4 = (idx & 63) * 4;
        if (c4 < ncols)
            cp16ca(s2u(s_wbuf + kk * 256 + c4), Wb + (size_t)kk * ldw + c4);
    }
}
__device__ __forceinline__ void fill_a8(const float* const* s_rp, int k0, float* s_abuf) {
    int tid = threadIdx.x;
    int r = tid >> 3, o = (tid & 7) * 4;
    cp16cg(s2u(s_abuf + r * 40 + o), s_rp[r] + k0 + o);
}

template <int K>
__device__ __forceinline__ void gemm8(const float* const* s_rp,
    const float* __restrict__ W, size_t ldw, int N, int bcol,
    ull* acc, float* s_w, float* s_a)
{
    constexpr int C = K / CHK;
    const int tid = threadIdx.x;
    const int lane = tid & 31;
    const int wid = tid >> 5;
    const int ncols = min(256, N - bcol);
    const float* W0 = W + bcol;

    __syncthreads();
    fill_w8(W0, ldw, ncols, s_w);
    fill_a8(s_rp, 0, s_a);
    cp_commit();
    if (C > 1) {
        fill_w8(W0 + (size_t)CHK * ldw, ldw, ncols, s_w + SWSZ);
        fill_a8(s_rp, CHK, s_a + SASZ);
        cp_commit();
    }

    const int chalf = (wid >> 2) * 128;
    const int rg = (wid & 3) * 8;
#pragma unroll 1
    for (int c = 0; c < C; c++) {
        if (c + 1 < C) cp_wait<1>(); else cp_wait<0>();
        __syncthreads();
        const float* sw = s_w + (c & 1) * SWSZ + chalf + lane * 4;
        const float* sa = s_a + (c & 1) * SASZ + rg * 40;
#pragma unroll
        for (int g = 0; g < CHK / 4; g++) {
            float4 w0 = *(const float4*)(sw + (4 * g + 0) * 256);
            float4 w1 = *(const float4*)(sw + (4 * g + 1) * 256);
            float4 w2 = *(const float4*)(sw + (4 * g + 2) * 256);
            float4 w3 = *(const float4*)(sw + (4 * g + 3) * 256);
            float4 av[8];
#pragma unroll
            for (int r = 0; r < 8; r++) av[r] = *(const float4*)(sa + r * 40 + 4 * g);
#pragma unroll
            for (int kk = 0; kk < 4; kk++) {
                float4 wv = (kk == 0) ? w0 : (kk == 1) ? w1 : (kk == 2) ? w2 : w3;
                ull wp0 = pk2(wv.x, wv.y), wp1 = pk2(wv.z, wv.w);
#pragma unroll
                for (int r = 0; r < 8; r++) {
                    float a = (kk == 0) ? av[r].x : (kk == 1) ? av[r].y
                              : (kk == 2) ? av[r].z : av[r].w;
                    ull ad = pk2(a, a);
                    fma2(acc[2 * r], wp0, ad);
                    fma2(acc[2 * r + 1], wp1, ad);
                }
            }
        }
        if (c + 2 < C) {
            __syncthreads();
            fill_w8(W0 + (size_t)(c + 2) * CHK * ldw, ldw, ncols, s_w + (c & 1) * SWSZ);
            fill_a8(s_rp, (c + 2) * CHK, s_a + (c & 1) * SASZ);
            cp_commit();
        }
    }
}

__device__ __forceinline__ void store8(ull* acc, float* Cp, int ldc, int bcol,
                                       int N, const float* __restrict__ bias) {
    int lane = threadIdx.x & 31, wid = threadIdx.x >> 5;
    int col0 = bcol + (wid >> 2) * 128 + lane * 4;
    int row0 = (wid & 3) * 8;
#pragma unroll
    for (int r = 0; r < 8; r++) {
#pragma unroll
        for (int p = 0; p < 2; p++) {
            float x0, x1;
            upk2(acc[2 * r + p], x0, x1);
            int c0 = col0 + 2 * p;
            if (c0 < N)
                Cp[(size_t)(row0 + r) * ldc + c0] = x0 + (bias ? bias[c0] : 0.f);
            if (c0 + 1 < N)
                Cp[(size_t)(row0 + r) * ldc + c0 + 1] = x1 + (bias ? bias[c0 + 1] : 0.f);
        }
    }
}

// ---------------- setup kernels ----------------
__global__ void __launch_bounds__(256) k_mean(const float* __restrict__ feat) {
    int b = blockIdx.x, f = blockIdx.y * 256 + threadIdx.x;
    const float* fb = feat + (size_t)b * NN * FF + f;
    float s = 0.f;
#pragma unroll 16
    for (int n = 0; n < NN; n++) s += fb[(size_t)n * FF];
    g_mean[b * FF + f] = s * (1.0f / NN);
    if (threadIdx.x == 0 && blockIdx.y == 0) g_amax[b] = (ull)(0xFFFFFFFFu - 1u);
    if (b == 0 && blockIdx.y == 0 && threadIdx.x == 0) { g_cnt = 0u; g_epoch = 0u; }
}

__global__ void __launch_bounds__(256) k_hc0(const float* __restrict__ Wh,
                                             const float* __restrict__ Wc) {
    extern __shared__ float sd[];
    __shared__ const float* s_rp[32];
    int m = blockIdx.x >> 4, v = blockIdx.x & 15;
    int ct = v >> 3, ks = v & 7;
    int koff = ks * 160;
    if (threadIdx.x < 32) s_rp[threadIdx.x] = g_mean + threadIdx.x * FF + koff;
    ull acc[16] = {};
    gemm8<160>(s_rp, (m ? Wc : Wh) + (size_t)koff * HH, HH, HH, ct * 256,
               acc, sd, sd + 2 * SWSZ);
    store8(acc, g_hcp[m * 8 + ks], HH, ct * 256, HH, nullptr);
}

__global__ void __launch_bounds__(256) k_hc0r(const float* __restrict__ bh,
                                              const float* __restrict__ bc) {
    int i = blockIdx.x * 256 + threadIdx.x;
    int j = i & 511;
    float sh = bh[j], sc = bc[j];
#pragma unroll
    for (int ks = 0; ks < 8; ks++) { sh += g_hcp[ks][i]; sc += g_hcp[8 + ks][i]; }
    g_h[0][i] = sh;
    g_c[0][i] = sc;
}

__global__ void __launch_bounds__(256) k_encproj(const float* __restrict__ feat,
                                                 const float* __restrict__ W2,
                                                 const float* __restrict__ b2) {
    extern __shared__ float sd[];
    __shared__ const float* s_rp[32];
    int bg = blockIdx.x >> 1, ct = blockIdx.x & 1;
    if (threadIdx.x < 32)
        s_rp[threadIdx.x] = feat + (size_t)(bg * 32 + threadIdx.x) * FF;
    ull acc[16] = {};
    gemm8<FF>(s_rp, W2, HH, HH, ct * 256, acc, sd, sd + 2 * SWSZ);
    store8(acc, g_encproj + (size_t)bg * 32 * HH, HH, ct * 256, HH, b2);
}

// ---------------- THE persistent kernel ----------------
__global__ void __launch_bounds__(256) k_persist(
    const float* __restrict__ feat, const float* __restrict__ emb,
    const float* __restrict__ W1, const float* __restrict__ b1,
    const float* __restrict__ Wg, const float* __restrict__ bg,
    const float* __restrict__ Wx, const float* __restrict__ Whh,
    const float* __restrict__ blstm,
    const float* __restrict__ Wout, const float* __restrict__ bout,
    const float* __restrict__ Va, float* __restrict__ out)
{
    extern __shared__ float sd[];
    __shared__ unsigned s_tok[32];
    __shared__ float s_sm[NN + 8];
    const int bx = blockIdx.x, tid = threadIdx.x;
    const int lane = tid & 31, wid = tid >> 5;
    unsigned ep = 0;

    for (int t = 0;; t++) {
        const int p = t & 1;

        // ---- P1: 110 GEMM units on h(t): hq, gate, Whh, Wout — all K-split ----
        {
            int id = bx;
            bool run = (id < 110);
            if (t == TT && id < 30) run = false;
            if (t == 0 && id >= 30) run = false;
            if (run) {
                ull acc[16] = {};
                int koff, bcol, N, ldc, stN;
                size_t ldw;
                const float* W;
                const float* bias = nullptr;
                float* dst;
                if (id < 4) {
                    int ct = id >> 1, ks = id & 1;
                    koff = ks * 256; bcol = ct * 256;
                    W = W1 + (size_t)koff * HH; ldw = HH;
                    dst = g_hqp[ks]; ldc = HH; N = HH; stN = HH;
                    if (ks == 0) bias = b1;
                } else if (id < 14) {
                    int v = id - 4, ct = v >> 1, ks = v & 1;
                    koff = ks * 256; bcol = ct * 256;
                    W = Wg + (size_t)koff * FF; ldw = FF;
                    dst = g_gatep[ks]; ldc = FF; N = FF; stN = FF;
                    if (ks == 0) bias = bg;
                } else if (id < 30) {
                    int v = id - 14, ct = v >> 1, ks = v & 1;
                    koff = ks * 256; bcol = ct * 256;
                    W = Whh + (size_t)koff * G4; ldw = G4;
                    dst = g_gpart[4 + ks]; ldc = G4; N = G4; stN = G4;
                } else {
                    int v = id - 30, ct = v >> 1, ks = v & 1;
                    koff = ks * 256; bcol = ct * 256;
                    W = Wout + (size_t)koff * VV; ldw = VV;
                    dst = g_lgp[ks]; ldc = VPAD; N = VV; stN = VPAD;
                }
                const int kof = koff;
                gemmq<256>([&](int r, int k) { return __ldcg(&g_h[p][r * HH + kof + k]); },
                           W, ldw, N, bcol, acc, sd);
                storeq(acc, dst, ldc, bcol, stN, bias);
            }
        }
        gbar(++ep);

        // ---- P2: logits finalize + argmax  ||  Bahdanau scores ----
        if (bx < 79) {
            if (t > 0) {
                const int tt = t - 1;
                int base = bx * 128;
#pragma unroll
                for (int rr = 0; rr < 4; rr++) {
                    int row = wid * 4 + rr;
                    int cc4 = base + lane * 4;
                    ull best = 0ull;
                    if (cc4 + 4 <= VV) {
                        float4 p0 = __ldcg((const float4*)(g_lgp[0] + (size_t)row * VPAD + cc4));
                        float4 p1 = __ldcg((const float4*)(g_lgp[1] + (size_t)row * VPAD + cc4));
                        float4 bo = *(const float4*)(bout + cc4);
                        float4 v;
                        v.x = p0.x + p1.x + bo.x; v.y = p0.y + p1.y + bo.y;
                        v.z = p0.z + p1.z + bo.z; v.w = p0.w + p1.w + bo.w;
                        *(float4*)(out + ((size_t)row * TT + tt) * VV + cc4) = v;
                        float vv[4] = {v.x, v.y, v.z, v.w};
#pragma unroll
                        for (int q = 0; q < 4; q++) {
                            ull key = ((ull)mono32(vv[q]) << 32) |
                                      (0xFFFFFFFFu - (unsigned)(cc4 + q));
                            if (key > best) best = key;
                        }
                    } else {
#pragma unroll
                        for (int q = 0; q < 4; q++) {
                            int cc = cc4 + q;
                            if (cc < VV) {
                                float v = __ldcg(&g_lgp[0][(size_t)row * VPAD + cc]) +
                                          __ldcg(&g_lgp[1][(size_t)row * VPAD + cc]) +
                                          bout[cc];
                                out[((size_t)row * TT + tt) * VV + cc] = v;
                                ull key = ((ull)mono32(v) << 32) |
                                          (0xFFFFFFFFu - (unsigned)cc);
                                if (key > best) best = key;
                            }
                        }
                    }
#pragma unroll
                    for (int m = 16; m; m >>= 1) {
                        ull o = __shfl_xor_sync(0xffffffffu, best, m);
                        if (o > best) best = o;
                    }
                    if (lane == 0) atomicMax(&g_amax[row], best);
                }
            }
        } else if (t < TT) {
            for (int j = (bx - 79) * 8 + wid; j < BB * NN; j += 69 * 8) {
                int b = j >> 6, n = j & 63;
                const float4* ep4 = (const float4*)(g_encproj + ((size_t)b * NN + n) * HH);
                const float4* h0 = (const float4*)(g_hqp[0] + b * HH);
                const float4* h1 = (const float4*)(g_hqp[1] + b * HH);
                const float4* va = (const float4*)Va;
                float s = 0.f;
#pragma unroll
                for (int i = 0; i < 4; i++) {
                    int e4 = lane + 32 * i;
                    float4 v = ep4[e4];
                    float4 q0 = __ldcg(h0 + e4);
                    float4 q1 = __ldcg(h1 + e4);
                    float4 a4 = va[e4];
                    s += fmaxf(v.x + q0.x + q1.x, 0.f) * a4.x;
                    s += fmaxf(v.y + q0.y + q1.y, 0.f) * a4.y;
                    s += fmaxf(v.z + q0.z + q1.z, 0.f) * a4.z;
                    s += fmaxf(v.w + q0.w + q1.w, 0.f) * a4.w;
                }
#pragma unroll
                for (int m = 16; m; m >>= 1) s += __shfl_xor_sync(0xffffffffu, s, m);
                if (lane == 0) g_scor[b * NN + n] = s;
            }
        }
        if (t == TT) return;
        gbar(++ep);

        // ---- P3: emb-GEMM (token, 4 k-slices of 128) || softmax + gated ctx ----
        if (bx < 32) {
            if (tid < 32)
                s_tok[tid] = 0xFFFFFFFFu -
                             (unsigned)(__ldcg(&g_amax[tid]) & 0xFFFFFFFFull);
            ull acc[16] = {};
            int ct = bx >> 2, ks = bx & 3;
            const int kof = ks * 128;
            gemmq<128>([&](int r, int k) { return emb[(size_t)s_tok[r] * EE + kof + k]; },
                       Wx + (size_t)kof * G4, G4, G4, ct * 256, acc, sd);
            storeq(acc, g_gpart[ks], G4, ct * 256, G4, ks == 0 ? blstm : nullptr);
        } else {
            float* s_wv = s_sm;
            float* s_red = s_sm + NN;
            for (int u = bx - 32; u < 160; u += 116) {
                int b = u / 5, fc = u - b * 5;
                __syncthreads();
                float v = 0.f;
                if (tid < 64) v = __ldcg(&g_scor[b * NN + tid]);
                float m = v;
#pragma unroll
                for (int s = 16; s; s >>= 1)
                    m = fmaxf(m, __shfl_xor_sync(0xffffffffu, m, s));
                if (tid < 64 && lane == 0) s_red[tid >> 5] = m;
                __syncthreads();
                if (tid < 64) {
                    float e = __expf(v - fmaxf(s_red[0], s_red[1]));
                    s_wv[tid] = e;
                    float sum = e;
#pragma unroll
                    for (int s = 16; s; s >>= 1)
                        sum += __shfl_xor_sync(0xffffffffu, sum, s);
                    if (lane == 0) s_red[2 + (tid >> 5)] = sum;
                }
                __syncthreads();
                float inv = 1.0f / (s_red[2] + s_red[3]);
                int f = fc * 256 + tid;
                const float* fb = feat + (size_t)b * NN * FF + f;
                float a = 0.f;
#pragma unroll 16
                for (int n = 0; n < NN; n++) a += s_wv[n] * fb[(size_t)n * FF];
                a *= inv;
                float gt = sigf(__ldcg(&g_gatep[0][b * FF + f]) +
                                __ldcg(&g_gatep[1][b * FF + f]));
                g_ctxg[b * FF + f] = a * gt;
                if (fc == 0 && tid < 64)
                    out[OFF_ATT + ((size_t)b * TT + t) * NN + tid] = s_wv[tid] * inv;
            }
        }
        gbar(++ep);

        // ---- P4: Wx-bottom 8 col-tiles x 10 k-slices of 128 ----
        if (bx < 80) {
            int ct = bx / 10, ks = bx - ct * 10;
            const int kof = ks * 128;
            ull acc[16] = {};
            gemmq<128>([&](int r, int k) { return __ldcg(&g_ctxg[r * FF + kof + k]); },
                       Wx + (size_t)(EE + kof) * G4, G4, G4, ct * 256, acc, sd);
            storeq(acc, g_gpart[6 + ks], G4, ct * 256, G4, nullptr);
        }
        gbar(++ep);

        // ---- P5: LSTM pointwise (sum 16 partials) + amax reset ----
        if (bx < 64) {
            int b = bx >> 1;
            int j = (bx & 1) * 256 + tid;
            float v[4];
#pragma unroll
            for (int g = 0; g < 4; g++) {
                float s = 0.f;
#pragma unroll
                for (int pt = 0; pt < 16; pt++)
                    s += __ldcg(&g_gpart[pt][b * G4 + g * HH + j]);
                v[g] = s;
            }
            float c_old = __ldcg(&g_c[p][b * HH + j]);
            float c2 = sigf(v[1]) * c_old + sigf(v[0]) * tanhf(v[2]);
            float h2 = sigf(v[3]) * tanhf(c2);
            g_c[p ^ 1][b * HH + j] = c2;
            g_h[p ^ 1][b * HH + j] = h2;
            if (t == TT - 1) {
                out[OFF_H + b * HH + j] = h2;
                out[OFF_C + b * HH + j] = c2;
            }
            if ((bx & 1) == 0 && tid == 0) g_amax[b] = 0ull;
        }
        gbar(++ep);
    }
}

// ---------------- launch ----------------
extern "C" void kernel_launch(void* const* d_in, const int* in_sizes, int n_in,
                              void* d_out, int out_size)
{
    int off = (n_in >= 21) ? 1 : 0;
    const float* feat  = (const float*)d_in[0];
    const float* emb   = (const float*)d_in[2 + off];
    const float* W1    = (const float*)d_in[3 + off];
    const float* b1    = (const float*)d_in[4 + off];
    const float* W2    = (const float*)d_in[5 + off];
    const float* b2    = (const float*)d_in[6 + off];
    const float* Va    = (const float*)d_in[7 + off];
    const float* Wh    = (const float*)d_in[9 + off];
    const float* bh    = (const float*)d_in[10 + off];
    const float* Wc    = (const float*)d_in[11 + off];
    const float* bc    = (const float*)d_in[12 + off];
    const float* Wg    = (const float*)d_in[13 + off];
    const float* bg    = (const float*)d_in[14 + off];
    const float* Wx    = (const float*)d_in[15 + off];
    const float* Whh   = (const float*)d_in[16 + off];
    const float* blstm = (const float*)d_in[17 + off];
    const float* Wout  = (const float*)d_in[18 + off];
    const float* bout  = (const float*)d_in[19 + off];
    float* out = (float*)d_out;

    const int SMB = (2 * SWSZ + 2 * SASZ) * 4;              // setup: 75,776 B
    const int SMP = (2 * WBQ + 256 * PAD) * 4;              // persist: 167,936 B
    cudaFuncSetAttribute(k_encproj, cudaFuncAttributeMaxDynamicSharedMemorySize, SMB);
    cudaFuncSetAttribute(k_hc0, cudaFuncAttributeMaxDynamicSharedMemorySize, SMB);
    cudaFuncSetAttribute(k_persist, cudaFuncAttributeMaxDynamicSharedMemorySize, SMP);

    k_mean<<<dim3(BB, 5), 256>>>(feat);
    k_hc0<<<32, 256, SMB>>>(Wh, Wc);
    k_hc0r<<<64, 256>>>(bh, bc);
    k_encproj<<<128, 256, SMB>>>(feat, W2, b2);
    k_persist<<<148, 256, SMP>>>(feat, emb, W1, b1, Wg, bg, Wx, Whh, blstm,
                                 Wout, bout, Va, out);
}

// round 12
// speedup vs baseline: 2.0654x; 1.1331x over previous
#include <cuda_runtime.h>
#include <cstdint>

typedef unsigned long long ull;

#define BB 32
#define NN 64
#define FF 1280
#define HH 512
#define EE 512
#define VV 10000
#define TT 80
#define G4 2048
#define VPAD 10240

// persist GEMM core
#define KC 64
#define PAD 36
#define WBQ (KC * 256)

// gemm8 setup core
#define CHK 32
#define SWSZ (CHK * 256)
#define SASZ (32 * 40)

// merged-phase groups
#define NA 48
#define NB 100

#define OFF_H   25600000ll
#define OFF_C   25616384ll
#define OFF_ATT 25632768ll

// ---------------- device state ----------------
__device__ float g_h[2][BB * HH];
__device__ float g_c[2][BB * HH];
__device__ float g_hqp[2][BB * HH];
__device__ float g_gatep[2][BB * FF];
__device__ float g_ctxg[BB * FF];
__device__ float g_scor[BB * NN];
__device__ float g_mean[BB * FF];
__device__ float g_encproj[BB * NN * HH];
__device__ float g_lgp[2][BB * VPAD];
__device__ float g_gpart[16][BB * G4];  // 0..3 emb, 4..5 Whh, 6..15 Wx-bottom
__device__ float g_hcp[16][BB * HH];
__device__ ull g_amax[BB];
__device__ unsigned g_cnt, g_epoch;
__device__ unsigned g_gcnt[4], g_gep[4];

// ---------------- helpers ----------------
__device__ __forceinline__ ull pk2(float lo, float hi) {
    ull r; asm("mov.b64 %0, {%1,%2};" : "=l"(r) : "f"(lo), "f"(hi)); return r;
}
__device__ __forceinline__ void upk2(ull v, float& lo, float& hi) {
    asm("mov.b64 {%0,%1}, %2;" : "=f"(lo), "=f"(hi) : "l"(v));
}
__device__ __forceinline__ void fma2(ull& d, ull a, ull b) {
    asm("fma.rn.f32x2 %0, %1, %2, %0;" : "+l"(d) : "l"(a), "l"(b));
}
__device__ __forceinline__ float sigf(float x) { return 1.0f / (1.0f + expf(-x)); }
__device__ __forceinline__ unsigned mono32(float f) {
    unsigned u = __float_as_uint(f);
    return (u & 0x80000000u) ? ~u : (u | 0x80000000u);
}
__device__ __forceinline__ uint32_t s2u(const void* p) {
    return (uint32_t)__cvta_generic_to_shared(p);
}
__device__ __forceinline__ void cp16ca(uint32_t dst, const void* src) {
    asm volatile("cp.async.ca.shared.global [%0], [%1], 16;" :: "r"(dst), "l"(src));
}
__device__ __forceinline__ void cp16cg(uint32_t dst, const void* src) {
    asm volatile("cp.async.cg.shared.global [%0], [%1], 16;" :: "r"(dst), "l"(src));
}
__device__ __forceinline__ void cp_commit() { asm volatile("cp.async.commit_group;"); }
template <int n>
__device__ __forceinline__ void cp_wait() {
    asm volatile("cp.async.wait_group %0;" :: "n"(n));
}
__device__ __forceinline__ unsigned ldcgu(const unsigned* p) {
    unsigned v; asm volatile("ld.global.cg.u32 %0, [%1];" : "=r"(v) : "l"(p)); return v;
}

// ---------------- barriers ----------------
__device__ __forceinline__ void gbar(unsigned target) {
    __threadfence();
    __syncthreads();
    if (threadIdx.x == 0) {
        unsigned old = atomicAdd(&g_cnt, 1u);
        if (old == 147u) {
            g_cnt = 0u;
            __threadfence();
            atomicAdd(&g_epoch, 1u);
        } else {
            while (ldcgu(&g_epoch) < target) __nanosleep(32);
        }
    }
    __syncthreads();
}
// group sub-barrier: `count` participants arrive; fires once per step.
__device__ __forceinline__ void gsub(int idx, unsigned count, unsigned target) {
    __threadfence();
    __syncthreads();
    if (threadIdx.x == 0) {
        unsigned old = atomicAdd(&g_gcnt[idx], 1u);
        if (old == count - 1u) {
            g_gcnt[idx] = 0u;
            __threadfence();
            atomicAdd(&g_gep[idx], 1u);
        } else {
            while (ldcgu(&g_gep[idx]) < target) __nanosleep(32);
        }
    }
    __syncthreads();
}

// ================= GEMM vQ (persist) ==========
__device__ __forceinline__ void fill_wq(const float* Wb, size_t ldw, int ncols,
                                        float* s_wbuf) {
    int tid = threadIdx.x;
    int kk = tid >> 6;
    int c4 = (tid & 63) * 4;
#pragma unroll
    for (int p = 0; p < 16; p++) {
        int kr = kk + p * 4;
        if (c4 < ncols)
            cp16ca(s2u(s_wbuf + kr * 256 + c4), Wb + (size_t)kr * ldw + c4);
    }
    cp_commit();
}

template <int K, class AElem>
__device__ __forceinline__ void gemmq(AElem aelem, const float* __restrict__ W,
    size_t ldw, int N, int bcol, ull* acc, float* s_dyn)
{
    constexpr int C = K / KC;
    const int tid = threadIdx.x;
    const int lane = tid & 31;
    const int wid = tid >> 5;
    float* s_w = s_dyn;
    float* s_a = s_dyn + 2 * WBQ;
    const int ncols = min(256, N - bcol);
    const float* W0 = W + bcol;

    __syncthreads();
    fill_wq(W0, ldw, ncols, s_w);
    if (C > 1) fill_wq(W0 + (size_t)KC * ldw, ldw, ncols, s_w + WBQ);

#pragma unroll 8
    for (int idx = tid; idx < 32 * K; idx += 256) {
        int r = idx / K, k = idx - r * K;
        s_a[k * PAD + r] = aelem(r, k);
    }

    const int chalf = (wid & 1) * 128;
    const int rg = (wid >> 1) * 8;
    const float* sa0 = s_a + rg;
#pragma unroll 1
    for (int c = 0; c < C; c++) {
        if (c + 1 < C) cp_wait<1>(); else cp_wait<0>();
        __syncthreads();
        const float* sw = s_w + (c & 1) * WBQ + chalf + lane * 4;
        const float* sac = sa0 + c * KC * PAD;
#pragma unroll 8
        for (int kk = 0; kk < KC; kk++) {
            float4 w4 = *(const float4*)(sw + kk * 256);
            float4 a0 = *(const float4*)(sac + kk * PAD);
            float4 a1 = *(const float4*)(sac + kk * PAD + 4);
            ull w01 = pk2(w4.x, w4.y), w23 = pk2(w4.z, w4.w);
#pragma unroll
            for (int r = 0; r < 4; r++) {
                float a = (r == 0) ? a0.x : (r == 1) ? a0.y : (r == 2) ? a0.z : a0.w;
                ull ad = pk2(a, a);
                fma2(acc[2 * r], w01, ad);
                fma2(acc[2 * r + 1], w23, ad);
            }
#pragma unroll
            for (int r = 0; r < 4; r++) {
                float a = (r == 0) ? a1.x : (r == 1) ? a1.y : (r == 2) ? a1.z : a1.w;
                ull ad = pk2(a, a);
                fma2(acc[8 + 2 * r], w01, ad);
                fma2(acc[8 + 2 * r + 1], w23, ad);
            }
        }
        if (c + 2 < C) {
            __syncthreads();
            fill_wq(W0 + (size_t)(c + 2) * KC * ldw, ldw, ncols, s_w + (c & 1) * WBQ);
        }
    }
}

__device__ __forceinline__ void storeq(ull* acc, float* Cp, int ldc, int bcol,
                                       int stN, const float* __restrict__ bias) {
    int lane = threadIdx.x & 31, wid = threadIdx.x >> 5;
    int col = bcol + (wid & 1) * 128 + lane * 4;
    int rg = (wid >> 1) * 8;
    if (col + 3 >= stN) return;
    float4 bb = bias ? *(const float4*)(bias + col) : make_float4(0.f, 0.f, 0.f, 0.f);
#pragma unroll
    for (int r = 0; r < 8; r++) {
        float v0, v1, v2, v3;
        upk2(acc[2 * r], v0, v1);
        upk2(acc[2 * r + 1], v2, v3);
        float4 o;
        o.x = v0 + bb.x; o.y = v1 + bb.y; o.z = v2 + bb.z; o.w = v3 + bb.w;
        *(float4*)(Cp + (size_t)(rg + r) * ldc + col) = o;
    }
}

// ================= GEMM v8 (setup kernels only) =================
__device__ __forceinline__ void fill_w8(const float* Wb, size_t ldw, int ncols,
                                        float* s_wbuf) {
    int tid = threadIdx.x;
#pragma unroll
    for (int p2 = 0; p2 < 8; p2++) {
        int idx = tid + p2 * 256;
        int kk = idx >> 6;
        int c4 = (idx & 63) * 4;
        if (c4 < ncols)
            cp16ca(s2u(s_wbuf + kk * 256 + c4), Wb + (size_t)kk * ldw + c4);
    }
}
__device__ __forceinline__ void fill_a8(const float* const* s_rp, int k0, float* s_abuf) {
    int tid = threadIdx.x;
    int r = tid >> 3, o = (tid & 7) * 4;
    cp16cg(s2u(s_abuf + r * 40 + o), s_rp[r] + k0 + o);
}

template <int K>
__device__ __forceinline__ void gemm8(const float* const* s_rp,
    const float* __restrict__ W, size_t ldw, int N, int bcol,
    ull* acc, float* s_w, float* s_a)
{
    constexpr int C = K / CHK;
    const int tid = threadIdx.x;
    const int lane = tid & 31;
    const int wid = tid >> 5;
    const int ncols = min(256, N - bcol);
    const float* W0 = W + bcol;

    __syncthreads();
    fill_w8(W0, ldw, ncols, s_w);
    fill_a8(s_rp, 0, s_a);
    cp_commit();
    if (C > 1) {
        fill_w8(W0 + (size_t)CHK * ldw, ldw, ncols, s_w + SWSZ);
        fill_a8(s_rp, CHK, s_a + SASZ);
        cp_commit();
    }

    const int chalf = (wid >> 2) * 128;
    const int rg = (wid & 3) * 8;
#pragma unroll 1
    for (int c = 0; c < C; c++) {
        if (c + 1 < C) cp_wait<1>(); else cp_wait<0>();
        __syncthreads();
        const float* sw = s_w + (c & 1) * SWSZ + chalf + lane * 4;
        const float* sa = s_a + (c & 1) * SASZ + rg * 40;
#pragma unroll
        for (int g = 0; g < CHK / 4; g++) {
            float4 w0 = *(const float4*)(sw + (4 * g + 0) * 256);
            float4 w1 = *(const float4*)(sw + (4 * g + 1) * 256);
            float4 w2 = *(const float4*)(sw + (4 * g + 2) * 256);
            float4 w3 = *(const float4*)(sw + (4 * g + 3) * 256);
            float4 av[8];
#pragma unroll
            for (int r = 0; r < 8; r++) av[r] = *(const float4*)(sa + r * 40 + 4 * g);
#pragma unroll
            for (int kk = 0; kk < 4; kk++) {
                float4 wv = (kk == 0) ? w0 : (kk == 1) ? w1 : (kk == 2) ? w2 : w3;
                ull wp0 = pk2(wv.x, wv.y), wp1 = pk2(wv.z, wv.w);
#pragma unroll
                for (int r = 0; r < 8; r++) {
                    float a = (kk == 0) ? av[r].x : (kk == 1) ? av[r].y
                              : (kk == 2) ? av[r].z : av[r].w;
                    ull ad = pk2(a, a);
                    fma2(acc[2 * r], wp0, ad);
                    fma2(acc[2 * r + 1], wp1, ad);
                }
            }
        }
        if (c + 2 < C) {
            __syncthreads();
            fill_w8(W0 + (size_t)(c + 2) * CHK * ldw, ldw, ncols, s_w + (c & 1) * SWSZ);
            fill_a8(s_rp, (c + 2) * CHK, s_a + (c & 1) * SASZ);
            cp_commit();
        }
    }
}

__device__ __forceinline__ void store8(ull* acc, float* Cp, int ldc, int bcol,
                                       int N, const float* __restrict__ bias) {
    int lane = threadIdx.x & 31, wid = threadIdx.x >> 5;
    int col0 = bcol + (wid >> 2) * 128 + lane * 4;
    int row0 = (wid & 3) * 8;
#pragma unroll
    for (int r = 0; r < 8; r++) {
#pragma unroll
        for (int p = 0; p < 2; p++) {
            float x0, x1;
            upk2(acc[2 * r + p], x0, x1);
            int c0 = col0 + 2 * p;
            if (c0 < N)
                Cp[(size_t)(row0 + r) * ldc + c0] = x0 + (bias ? bias[c0] : 0.f);
            if (c0 + 1 < N)
                Cp[(size_t)(row0 + r) * ldc + c0 + 1] = x1 + (bias ? bias[c0 + 1] : 0.f);
        }
    }
}

// ---------------- setup kernels ----------------
__global__ void __launch_bounds__(256) k_mean(const float* __restrict__ feat) {
    int b = blockIdx.x, f = blockIdx.y * 256 + threadIdx.x;
    const float* fb = feat + (size_t)b * NN * FF + f;
    float s = 0.f;
#pragma unroll 16
    for (int n = 0; n < NN; n++) s += fb[(size_t)n * FF];
    g_mean[b * FF + f] = s * (1.0f / NN);
    if (threadIdx.x == 0 && blockIdx.y == 0) g_amax[b] = (ull)(0xFFFFFFFFu - 1u);
    if (b == 0 && blockIdx.y == 0 && threadIdx.x < 4) {
        if (threadIdx.x == 0) { g_cnt = 0u; g_epoch = 0u; }
        g_gcnt[threadIdx.x] = 0u;
        g_gep[threadIdx.x] = 0u;
    }
}

__global__ void __launch_bounds__(256) k_hc0(const float* __restrict__ Wh,
                                             const float* __restrict__ Wc) {
    extern __shared__ float sd[];
    __shared__ const float* s_rp[32];
    int m = blockIdx.x >> 4, v = blockIdx.x & 15;
    int ct = v >> 3, ks = v & 7;
    int koff = ks * 160;
    if (threadIdx.x < 32) s_rp[threadIdx.x] = g_mean + threadIdx.x * FF + koff;
    ull acc[16] = {};
    gemm8<160>(s_rp, (m ? Wc : Wh) + (size_t)koff * HH, HH, HH, ct * 256,
               acc, sd, sd + 2 * SWSZ);
    store8(acc, g_hcp[m * 8 + ks], HH, ct * 256, HH, nullptr);
}

__global__ void __launch_bounds__(256) k_hc0r(const float* __restrict__ bh,
                                              const float* __restrict__ bc) {
    int i = blockIdx.x * 256 + threadIdx.x;
    int j = i & 511;
    float sh = bh[j], sc = bc[j];
#pragma unroll
    for (int ks = 0; ks < 8; ks++) { sh += g_hcp[ks][i]; sc += g_hcp[8 + ks][i]; }
    g_h[0][i] = sh;
    g_c[0][i] = sc;
}

__global__ void __launch_bounds__(256) k_encproj(const float* __restrict__ feat,
                                                 const float* __restrict__ W2,
                                                 const float* __restrict__ b2) {
    extern __shared__ float sd[];
    __shared__ const float* s_rp[32];
    int bg = blockIdx.x >> 1, ct = blockIdx.x & 1;
    if (threadIdx.x < 32)
        s_rp[threadIdx.x] = feat + (size_t)(bg * 32 + threadIdx.x) * FF;
    ull acc[16] = {};
    gemm8<FF>(s_rp, W2, HH, HH, ct * 256, acc, sd, sd + 2 * SWSZ);
    store8(acc, g_encproj + (size_t)bg * 32 * HH, HH, ct * 256, HH, b2);
}

// ---------------- logits finalize + argmax (one 128-col chunk) ----------------
__device__ __forceinline__ void finalize_chunk(int ch, int tt,
    const float* __restrict__ bout, float* __restrict__ out,
    int lane, int wid)
{
    int base = ch * 128;
#pragma unroll
    for (int rr = 0; rr < 4; rr++) {
        int row = wid * 4 + rr;
        int cc4 = base + lane * 4;
        ull best = 0ull;
        if (cc4 + 4 <= VV) {
            float4 p0 = __ldcg((const float4*)(g_lgp[0] + (size_t)row * VPAD + cc4));
            float4 p1 = __ldcg((const float4*)(g_lgp[1] + (size_t)row * VPAD + cc4));
            float4 bo = *(const float4*)(bout + cc4);
            float4 v;
            v.x = p0.x + p1.x + bo.x; v.y = p0.y + p1.y + bo.y;
            v.z = p0.z + p1.z + bo.z; v.w = p0.w + p1.w + bo.w;
            *(float4*)(out + ((size_t)row * TT + tt) * VV + cc4) = v;
            float vv[4] = {v.x, v.y, v.z, v.w};
#pragma unroll
            for (int q = 0; q < 4; q++) {
                ull key = ((ull)mono32(vv[q]) << 32) |
                          (0xFFFFFFFFu - (unsigned)(cc4 + q));
                if (key > best) best = key;
            }
        } else {
#pragma unroll
            for (int q = 0; q < 4; q++) {
                int cc = cc4 + q;
                if (cc < VV) {
                    float v = __ldcg(&g_lgp[0][(size_t)row * VPAD + cc]) +
                              __ldcg(&g_lgp[1][(size_t)row * VPAD + cc]) + bout[cc];
                    out[((size_t)row * TT + tt) * VV + cc] = v;
                    ull key = ((ull)mono32(v) << 32) | (0xFFFFFFFFu - (unsigned)cc);
                    if (key > best) best = key;
                }
            }
        }
#pragma unroll
        for (int m = 16; m; m >>= 1) {
            ull o = __shfl_xor_sync(0xffffffffu, best, m);
            if (o > best) best = o;
        }
        if (lane == 0) atomicMax(&g_amax[row], best);
    }
}

// ---------------- THE persistent kernel ----------------
__global__ void __launch_bounds__(256) k_persist(
    const float* __restrict__ feat, const float* __restrict__ emb,
    const float* __restrict__ W1, const float* __restrict__ b1,
    const float* __restrict__ Wg, const float* __restrict__ bg,
    const float* __restrict__ Wx, const float* __restrict__ Whh,
    const float* __restrict__ blstm,
    const float* __restrict__ Wout, const float* __restrict__ bout,
    const float* __restrict__ Va, float* __restrict__ out)
{
    extern __shared__ float sd[];
    __shared__ unsigned s_tok[32];
    __shared__ float s_sm[NN + 8];
    const int bx = blockIdx.x, tid = threadIdx.x;
    const int lane = tid & 31, wid = tid >> 5;
    unsigned ep = 0;

    for (int t = 0;; t++) {
        const int p = t & 1;

        // ---- P1: 110 GEMM units on h(t): hq, gate, Whh, Wout — all K-split ----
        {
            int id = bx;
            bool run = (id < 110);
            if (t == TT && id < 30) run = false;
            if (t == 0 && id >= 30) run = false;
            if (run) {
                ull acc[16] = {};
                int koff, bcol, N, ldc, stN;
                size_t ldw;
                const float* W;
                const float* bias = nullptr;
                float* dst;
                if (id < 4) {
                    int ct = id >> 1, ks = id & 1;
                    koff = ks * 256; bcol = ct * 256;
                    W = W1 + (size_t)koff * HH; ldw = HH;
                    dst = g_hqp[ks]; ldc = HH; N = HH; stN = HH;
                    if (ks == 0) bias = b1;
                } else if (id < 14) {
                    int v = id - 4, ct = v >> 1, ks = v & 1;
                    koff = ks * 256; bcol = ct * 256;
                    W = Wg + (size_t)koff * FF; ldw = FF;
                    dst = g_gatep[ks]; ldc = FF; N = FF; stN = FF;
                    if (ks == 0) bias = bg;
                } else if (id < 30) {
                    int v = id - 14, ct = v >> 1, ks = v & 1;
                    koff = ks * 256; bcol = ct * 256;
                    W = Whh + (size_t)koff * G4; ldw = G4;
                    dst = g_gpart[4 + ks]; ldc = G4; N = G4; stN = G4;
                } else {
                    int v = id - 30, ct = v >> 1, ks = v & 1;
                    koff = ks * 256; bcol = ct * 256;
                    W = Wout + (size_t)koff * VV; ldw = VV;
                    dst = g_lgp[ks]; ldc = VPAD; N = VV; stN = VPAD;
                }
                const int kof = koff;
                gemmq<256>([&](int r, int k) { return __ldcg(&g_h[p][r * HH + kof + k]); },
                           W, ldw, N, bcol, acc, sd);
                storeq(acc, dst, ldc, bcol, stN, bias);
            }
        }
        gbar(++ep);

        if (t == TT) {
            // tail: finalize logits for t-1 = 79, then exit
            if (bx < NA) {
                for (int ch = bx; ch < 79; ch += NA)
                    finalize_chunk(ch, t - 1, bout, out, lane, wid);
            }
            return;
        }

        // ---- Merged phase: chain A (blocks 0..NA-1) || chain B (NA..147) ----
        if (bx < NA) {
            // A1: logits(t-1) finalize + argmax
            if (t > 0) {
                for (int ch = bx; ch < 79; ch += NA)
                    finalize_chunk(ch, t - 1, bout, out, lane, wid);
            }
            gsub(1, NA, (unsigned)(t + 1));
            // A2: emb-GEMM (token) -> gpart[0..3], 32 units (8ct x 4ks, K=128)
            if (bx < 32) {
                if (tid < 32)
                    s_tok[tid] = 0xFFFFFFFFu -
                                 (unsigned)(__ldcg(&g_amax[tid]) & 0xFFFFFFFFull);
                ull acc[16] = {};
                int ct = bx >> 2, ks = bx & 3;
                const int kof = ks * 128;
                gemmq<128>([&](int r, int k)
                           { return emb[(size_t)s_tok[r] * EE + kof + k]; },
                           Wx + (size_t)kof * G4, G4, G4, ct * 256, acc, sd);
                storeq(acc, g_gpart[ks], G4, ct * 256, G4, ks == 0 ? blstm : nullptr);
            }
        } else {
            // B1: Bahdanau scores
            for (int j = (bx - NA) * 8 + wid; j < BB * NN; j += NB * 8) {
                int b = j >> 6, n = j & 63;
                const float4* ep4 = (const float4*)(g_encproj + ((size_t)b * NN + n) * HH);
                const float4* h0 = (const float4*)(g_hqp[0] + b * HH);
                const float4* h1 = (const float4*)(g_hqp[1] + b * HH);
                const float4* va = (const float4*)Va;
                float s = 0.f;
#pragma unroll
                for (int i = 0; i < 4; i++) {
                    int e4 = lane + 32 * i;
                    float4 v = ep4[e4];
                    float4 q0 = __ldcg(h0 + e4);
                    float4 q1 = __ldcg(h1 + e4);
                    float4 a4 = va[e4];
                    s += fmaxf(v.x + q0.x + q1.x, 0.f) * a4.x;
                    s += fmaxf(v.y + q0.y + q1.y, 0.f) * a4.y;
                    s += fmaxf(v.z + q0.z + q1.z, 0.f) * a4.z;
                    s += fmaxf(v.w + q0.w + q1.w, 0.f) * a4.w;
                }
#pragma unroll
                for (int m = 16; m; m >>= 1) s += __shfl_xor_sync(0xffffffffu, s, m);
                if (lane == 0) g_scor[b * NN + n] = s;
            }
            gsub(2, NB, (unsigned)(t + 1));
            // B2: softmax (redundant per block) + gated context
            {
                float* s_wv = s_sm;
                float* s_red = s_sm + NN;
                for (int u = bx - NA; u < 160; u += NB) {
                    int b = u / 5, fc = u - b * 5;
                    __syncthreads();
                    float v = 0.f;
                    if (tid < 64) v = __ldcg(&g_scor[b * NN + tid]);
                    float m = v;
#pragma unroll
                    for (int s = 16; s; s >>= 1)
                        m = fmaxf(m, __shfl_xor_sync(0xffffffffu, m, s));
                    if (tid < 64 && lane == 0) s_red[tid >> 5] = m;
                    __syncthreads();
                    if (tid < 64) {
                        float e = __expf(v - fmaxf(s_red[0], s_red[1]));
                        s_wv[tid] = e;
                        float sum = e;
#pragma unroll
                        for (int s = 16; s; s >>= 1)
                            sum += __shfl_xor_sync(0xffffffffu, sum, s);
                        if (lane == 0) s_red[2 + (tid >> 5)] = sum;
                    }
                    __syncthreads();
                    float inv = 1.0f / (s_red[2] + s_red[3]);
                    int f = fc * 256 + tid;
                    const float* fb = feat + (size_t)b * NN * FF + f;
                    float a = 0.f;
#pragma unroll 16
                    for (int n = 0; n < NN; n++) a += s_wv[n] * fb[(size_t)n * FF];
                    a *= inv;
                    float gt = sigf(__ldcg(&g_gatep[0][b * FF + f]) +
                                    __ldcg(&g_gatep[1][b * FF + f]));
                    g_ctxg[b * FF + f] = a * gt;
                    if (fc == 0 && tid < 64)
                        out[OFF_ATT + ((size_t)b * TT + t) * NN + tid] = s_wv[tid] * inv;
                }
            }
            gsub(3, NB, (unsigned)(t + 1));
            // B3: Wx-bottom 8 col-tiles x 10 k-slices of 128 (80 units)
            {
                int u = bx - NA;
                if (u < 80) {
                    int ct = u / 10, ks = u - ct * 10;
                    const int kof = ks * 128;
                    ull acc[16] = {};
                    gemmq<128>([&](int r, int k)
                               { return __ldcg(&g_ctxg[r * FF + kof + k]); },
                               Wx + (size_t)(EE + kof) * G4, G4, G4, ct * 256, acc, sd);
                    storeq(acc, g_gpart[6 + ks], G4, ct * 256, G4, nullptr);
                }
            }
        }
        gbar(++ep);

        // ---- P5: LSTM pointwise (sum 16 partials) + amax reset ----
        if (bx < 64) {
            int b = bx >> 1;
            int j = (bx & 1) * 256 + tid;
            float v[4];
#pragma unroll
            for (int g = 0; g < 4; g++) {
                float s = 0.f;
#pragma unroll
                for (int pt = 0; pt < 16; pt++)
                    s += __ldcg(&g_gpart[pt][b * G4 + g * HH + j]);
                v[g] = s;
            }
            float c_old = __ldcg(&g_c[p][b * HH + j]);
            float c2 = sigf(v[1]) * c_old + sigf(v[0]) * tanhf(v[2]);
            float h2 = sigf(v[3]) * tanhf(c2);
            g_c[p ^ 1][b * HH + j] = c2;
            g_h[p ^ 1][b * HH + j] = h2;
            if (t == TT - 1) {
                out[OFF_H + b * HH + j] = h2;
                out[OFF_C + b * HH + j] = c2;
            }
            if ((bx & 1) == 0 && tid == 0) g_amax[b] = 0ull;
        }
        gbar(++ep);
    }
}

// ---------------- launch ----------------
extern "C" void kernel_launch(void* const* d_in, const int* in_sizes, int n_in,
                              void* d_out, int out_size)
{
    int off = (n_in >= 21) ? 1 : 0;
    const float* feat  = (const float*)d_in[0];
    const float* emb   = (const float*)d_in[2 + off];
    const float* W1    = (const float*)d_in[3 + off];
    const float* b1    = (const float*)d_in[4 + off];
    const float* W2    = (const float*)d_in[5 + off];
    const float* b2    = (const float*)d_in[6 + off];
    const float* Va    = (const float*)d_in[7 + off];
    const float* Wh    = (const float*)d_in[9 + off];
    const float* bh    = (const float*)d_in[10 + off];
    const float* Wc    = (const float*)d_in[11 + off];
    const float* bc    = (const float*)d_in[12 + off];
    const float* Wg    = (const float*)d_in[13 + off];
    const float* bg    = (const float*)d_in[14 + off];
    const float* Wx    = (const float*)d_in[15 + off];
    const float* Whh   = (const float*)d_in[16 + off];
    const float* blstm = (const float*)d_in[17 + off];
    const float* Wout  = (const float*)d_in[18 + off];
    const float* bout  = (const float*)d_in[19 + off];
    float* out = (float*)d_out;

    const int SMB = (2 * SWSZ + 2 * SASZ) * 4;              // setup: 75,776 B
    const int SMP = (2 * WBQ + 256 * PAD) * 4;              // persist: 167,936 B
    cudaFuncSetAttribute(k_encproj, cudaFuncAttributeMaxDynamicSharedMemorySize, SMB);
    cudaFuncSetAttribute(k_hc0, cudaFuncAttributeMaxDynamicSharedMemorySize, SMB);
    cudaFuncSetAttribute(k_persist, cudaFuncAttributeMaxDynamicSharedMemorySize, SMP);

    k_mean<<<dim3(BB, 5), 256>>>(feat);
    k_hc0<<<32, 256, SMB>>>(Wh, Wc);
    k_hc0r<<<64, 256>>>(bh, bc);
    k_encproj<<<128, 256, SMB>>>(feat, W2, b2);
    k_persist<<<148, 256, SMP>>>(feat, emb, W1, b1, Wg, bg, Wx, Whh, blstm,
                                 Wout, bout, Va, out);
}